// round 3
// baseline (speedup 1.0000x reference)
#include <cuda_runtime.h>
#include <mma.h>
#include <cstdint>
#include <math.h>

using namespace nvcuda;

#define BATCH 8
#define SEQ 1024
#define DMODEL 768
#define NHEAD 16
#define HDIM 48
#define MROWS (BATCH*SEQ)

// ---------------- scratch (allocation-free rule: device globals) -----------------
__device__ float g_Q[MROWS*DMODEL];   // [B,H,S,PD]
__device__ float g_K[MROWS*DMODEL];   // [B,H,S,PD]
__device__ float g_V[MROWS*DMODEL];   // [B,H,S,PD]
__device__ float g_A[MROWS*DMODEL];   // [B,S,D]

// ---------------- wmma tf32 GEMM ------------------------------------------------
// C[128x128] tiles, K=768, BK=32, 256 threads (8 warps, 4x2), warp tile 32x64.
// mode 0: A=X [8192,768], B = {Wq|Wk|Wv} [768,768] by N range, out->g_Q/K/V remapped
// mode 1: A=g_A,          B = Wo,                          out->d_out
#define BK 32
#define LDA 36
#define LDB 132
#define LDC 132
// dynamic smem: phase1 tiles (A:128*36, B:32*132 floats), phase2 stage C 128*132
#define SM_BYTES (128*LDC*4)

__global__ __launch_bounds__(256)
void gemm_wmma(const float* __restrict__ Ain,
               const float* __restrict__ Bq, const float* __restrict__ Bk,
               const float* __restrict__ Bv,
               const float* __restrict__ b0, const float* __restrict__ b1,
               const float* __restrict__ b2,
               float* __restrict__ outp, int mode)
{
    extern __shared__ float smem[];
    float* As = smem;               // [128][LDA]
    float* Bs = smem + 128*LDA;     // [BK][LDB]

    const int tid  = threadIdx.x;
    const int warp = tid >> 5;
    const int wm   = warp >> 1;     // 0..3  (32-row strips)
    const int wn   = warp & 1;      // 0..1  (64-col strips)

    const int mTile = blockIdx.y * 128;
    const int nGlob = blockIdx.x * 128;

    const float* A = (mode == 0) ? Ain : g_A;
    const float* B; const float* bias; int nTile;
    if (mode == 0) {
        const int which = nGlob / DMODEL;
        B    = (which == 0) ? Bq : (which == 1) ? Bk : Bv;
        bias = (which == 0) ? b0 : (which == 1) ? b1 : b2;
        nTile = nGlob - which*DMODEL;
    } else { B = Bq; bias = b0; nTile = nGlob; }

    wmma::fragment<wmma::accumulator, 16, 16, 8, float> c[2][4];
    #pragma unroll
    for (int i = 0; i < 2; i++)
        #pragma unroll
        for (int j = 0; j < 4; j++)
            wmma::fill_fragment(c[i][j], 0.0f);

    for (int k0 = 0; k0 < DMODEL; k0 += BK) {
        // A tile 128x32: 1024 float4, 4 per thread
        #pragma unroll
        for (int t = 0; t < 4; t++) {
            const int idx = tid + t*256;
            const int row = idx >> 3, c4 = (idx & 7) << 2;
            *(float4*)&As[row*LDA + c4] =
                *(const float4*)&A[(size_t)(mTile + row)*DMODEL + k0 + c4];
        }
        // B tile 32x128: 1024 float4, 4 per thread
        #pragma unroll
        for (int t = 0; t < 4; t++) {
            const int idx = tid + t*256;
            const int row = idx >> 5, c4 = (idx & 31) << 2;
            *(float4*)&Bs[row*LDB + c4] =
                *(const float4*)&B[(size_t)(k0 + row)*DMODEL + nTile + c4];
        }
        __syncthreads();

        #pragma unroll
        for (int kk = 0; kk < BK/8; kk++) {
            wmma::fragment<wmma::matrix_a, 16, 16, 8, wmma::precision::tf32, wmma::row_major> a[2];
            wmma::fragment<wmma::matrix_b, 16, 16, 8, wmma::precision::tf32, wmma::row_major> b[4];
            #pragma unroll
            for (int i = 0; i < 2; i++) {
                wmma::load_matrix_sync(a[i], &As[(wm*32 + i*16)*LDA + kk*8], LDA);
                #pragma unroll
                for (int e = 0; e < a[i].num_elements; e++)
                    a[i].x[e] = wmma::__float_to_tf32(a[i].x[e]);
            }
            #pragma unroll
            for (int j = 0; j < 4; j++) {
                wmma::load_matrix_sync(b[j], &Bs[(kk*8)*LDB + wn*64 + j*16], LDB);
                #pragma unroll
                for (int e = 0; e < b[j].num_elements; e++)
                    b[j].x[e] = wmma::__float_to_tf32(b[j].x[e]);
            }
            #pragma unroll
            for (int i = 0; i < 2; i++)
                #pragma unroll
                for (int j = 0; j < 4; j++)
                    wmma::mma_sync(c[i][j], a[i], b[j], c[i][j]);
        }
        __syncthreads();
    }

    // stage C in smem, then coalesced bias+remap stores
    float* stage = smem;   // [128][LDC]
    #pragma unroll
    for (int i = 0; i < 2; i++)
        #pragma unroll
        for (int j = 0; j < 4; j++)
            wmma::store_matrix_sync(&stage[(wm*32 + i*16)*LDC + wn*64 + j*16],
                                    c[i][j], LDC, wmma::mem_row_major);
    __syncthreads();

    if (mode == 0) {
        const int which = nGlob / DMODEL;
        float* outg = (which == 0) ? g_Q : (which == 1) ? g_K : g_V;
        #pragma unroll
        for (int t = 0; t < 16; t++) {
            const int g = tid + t*256;
            const int row = g >> 5, cc = (g & 31) << 2;
            float4 v = *(float4*)&stage[row*LDC + cc];
            const int np = nTile + cc;                 // 4-col group never straddles a head
            const int h = np / HDIM, pd = np % HDIM;
            const float4 bb = *(const float4*)&bias[np];
            v.x += bb.x; v.y += bb.y; v.z += bb.z; v.w += bb.w;
            const int m = mTile + row;
            const int b = m >> 10, s = m & 1023;
            *(float4*)&outg[(((size_t)b*NHEAD + h)*SEQ + s)*HDIM + pd] = v;
        }
    } else {
        #pragma unroll
        for (int t = 0; t < 16; t++) {
            const int g = tid + t*256;
            const int row = g >> 5, cc = (g & 31) << 2;
            float4 v = *(float4*)&stage[row*LDC + cc];
            const float4 bb = *(const float4*)&bias[nTile + cc];
            v.x += bb.x; v.y += bb.y; v.z += bb.z; v.w += bb.w;
            *(float4*)&outp[(size_t)(mTile + row)*DMODEL + nTile + cc] = v;
        }
    }
}

// ---------------- Flash attention (fp32, vectorized smem) ------------------------
#define AM 64
#define AN 32

__global__ __launch_bounds__(256)
void attn_kernel()
{
    __shared__ float sQ[AM*HDIM];
    __shared__ float sK[AN*HDIM];
    __shared__ float sV[AN*HDIM];
    __shared__ float sS[AM*33];

    const int bh = blockIdx.y;
    const int q0 = blockIdx.x * AM;
    const float* Qp = g_Q + (size_t)bh * SEQ * HDIM;
    const float* Kp = g_K + (size_t)bh * SEQ * HDIM;
    const float* Vp = g_V + (size_t)bh * SEQ * HDIM;

    const int tid = threadIdx.x;

    {   // Q tile: 64x48 = 768 float4
        const float4* src = (const float4*)(Qp + (size_t)q0 * HDIM);
        float4* dst = (float4*)sQ;
        for (int i = tid; i < AM*HDIM/4; i += 256) dst[i] = src[i];
    }

    const int r  = tid >> 2;
    const int qd = tid & 3;

    float m_i = -1e30f, l_i = 0.f;
    float4 a0 = {0,0,0,0}, a1 = {0,0,0,0}, a2 = {0,0,0,0};
    const float scale = rsqrtf((float)HDIM);

    for (int kt = 0; kt < SEQ/AN; kt++) {
        __syncthreads();
        {   // K/V tiles: 32x48 = 384 float4 each
            const float4* srck = (const float4*)(Kp + (size_t)kt*AN*HDIM);
            const float4* srcv = (const float4*)(Vp + (size_t)kt*AN*HDIM);
            float4* dk = (float4*)sK; float4* dv = (float4*)sV;
            for (int i = tid; i < AN*HDIM/4; i += 256) { dk[i] = srck[i]; dv[i] = srcv[i]; }
        }
        __syncthreads();

        float sv[8];
        #pragma unroll
        for (int jj = 0; jj < 8; jj++) sv[jj] = 0.f;
        #pragma unroll
        for (int d0 = 0; d0 < HDIM; d0 += 4) {
            const float4 q4 = *(const float4*)&sQ[r*HDIM + d0];
            #pragma unroll
            for (int jj = 0; jj < 8; jj++) {
                const int c = qd*8 + jj;
                const float4 k4 = *(const float4*)&sK[c*HDIM + d0];
                sv[jj] = fmaf(q4.x, k4.x, fmaf(q4.y, k4.y, fmaf(q4.z, k4.z, fmaf(q4.w, k4.w, sv[jj]))));
            }
        }
        float mloc = -1e30f;
        #pragma unroll
        for (int jj = 0; jj < 8; jj++) { sv[jj] *= scale; mloc = fmaxf(mloc, sv[jj]); }
        mloc = fmaxf(mloc, __shfl_xor_sync(0xffffffffu, mloc, 1));
        mloc = fmaxf(mloc, __shfl_xor_sync(0xffffffffu, mloc, 2));
        const float m_new = fmaxf(m_i, mloc);
        const float corr  = __expf(m_i - m_new);

        float lloc = 0.f;
        #pragma unroll
        for (int jj = 0; jj < 8; jj++) {
            const float p = __expf(sv[jj] - m_new);
            sS[r*33 + qd*8 + jj] = p;
            lloc += p;
        }
        lloc += __shfl_xor_sync(0xffffffffu, lloc, 1);
        lloc += __shfl_xor_sync(0xffffffffu, lloc, 2);
        l_i = l_i * corr + lloc;
        m_i = m_new;

        __syncthreads();

        a0.x *= corr; a0.y *= corr; a0.z *= corr; a0.w *= corr;
        a1.x *= corr; a1.y *= corr; a1.z *= corr; a1.w *= corr;
        a2.x *= corr; a2.y *= corr; a2.z *= corr; a2.w *= corr;
        #pragma unroll
        for (int n = 0; n < AN; n++) {
            const float p = sS[r*33 + n];
            const float* vb = &sV[n*HDIM + qd*12];
            const float4 v0 = *(const float4*)(vb);
            const float4 v1 = *(const float4*)(vb + 4);
            const float4 v2 = *(const float4*)(vb + 8);
            a0.x = fmaf(p, v0.x, a0.x); a0.y = fmaf(p, v0.y, a0.y);
            a0.z = fmaf(p, v0.z, a0.z); a0.w = fmaf(p, v0.w, a0.w);
            a1.x = fmaf(p, v1.x, a1.x); a1.y = fmaf(p, v1.y, a1.y);
            a1.z = fmaf(p, v1.z, a1.z); a1.w = fmaf(p, v1.w, a1.w);
            a2.x = fmaf(p, v2.x, a2.x); a2.y = fmaf(p, v2.y, a2.y);
            a2.z = fmaf(p, v2.z, a2.z); a2.w = fmaf(p, v2.w, a2.w);
        }
    }

    const int b = bh / NHEAD, h = bh % NHEAD;
    const float inv = 1.f / l_i;
    float* op = &g_A[((size_t)b*SEQ + q0 + r)*DMODEL + h*HDIM + qd*12];
    a0.x *= inv; a0.y *= inv; a0.z *= inv; a0.w *= inv;
    a1.x *= inv; a1.y *= inv; a1.z *= inv; a1.w *= inv;
    a2.x *= inv; a2.y *= inv; a2.z *= inv; a2.w *= inv;
    *(float4*)(op)     = a0;
    *(float4*)(op + 4) = a1;
    *(float4*)(op + 8) = a2;
}

// ---------------- launch ---------------------------------------------------------
extern "C" void kernel_launch(void* const* d_in, const int* in_sizes, int n_in,
                              void* d_out, int out_size)
{
    const float* X  = (const float*)d_in[0];
    const float* Wq = (const float*)d_in[1];
    const float* bq = (const float*)d_in[2];
    const float* Wk = (const float*)d_in[3];
    const float* bk = (const float*)d_in[4];
    const float* Wv = (const float*)d_in[5];
    const float* bv = (const float*)d_in[6];
    const float* Wo = (const float*)d_in[7];
    const float* bo = (const float*)d_in[8];
    float* out = (float*)d_out;

    static int attr_done = 0;
    if (!attr_done) {
        cudaFuncSetAttribute(gemm_wmma, cudaFuncAttributeMaxDynamicSharedMemorySize, SM_BYTES);
        attr_done = 1;
    }

    dim3 gQKV(3*DMODEL/128, MROWS/128);           // 18 x 64
    gemm_wmma<<<gQKV, 256, SM_BYTES>>>(X, Wq, Wk, Wv, bq, bk, bv, nullptr, 0);

    dim3 gAttn(SEQ/AM, BATCH*NHEAD);              // 16 x 128
    attn_kernel<<<gAttn, 256>>>();

    dim3 gO(DMODEL/128, MROWS/128);               // 6 x 64
    gemm_wmma<<<gO, 256, SM_BYTES>>>(X, Wo, nullptr, nullptr, bo, nullptr, nullptr, out, 1);
}

// round 4
// speedup vs baseline: 2.9470x; 2.9470x over previous
#include <cuda_runtime.h>
#include <cuda_pipeline.h>
#include <mma.h>
#include <cstdint>
#include <math.h>

using namespace nvcuda;

#define BATCH 8
#define SEQ 1024
#define DMODEL 768
#define NHEAD 16
#define HDIM 48
#define MROWS (BATCH*SEQ)

// ---------------- scratch (allocation-free rule: device globals) -----------------
__device__ float g_Q[MROWS*DMODEL];   // [B,H,S,PD]
__device__ float g_K[MROWS*DMODEL];   // [B,H,S,PD]
__device__ float g_V[MROWS*DMODEL];   // [B,H,S,PD]
__device__ float g_A[MROWS*DMODEL];   // [B,S,D]

// ---------------- packed f32x2 helpers -------------------------------------------
__device__ __forceinline__ uint64_t pack2(float x) {
    uint64_t r; asm("mov.b64 %0, {%1,%1};" : "=l"(r) : "f"(x)); return r;
}
__device__ __forceinline__ void fma2(uint64_t& d, uint64_t a, uint64_t b) {
    asm("fma.rn.f32x2 %0, %1, %2, %0;" : "+l"(d) : "l"(a), "l"(b));
}
__device__ __forceinline__ void mul2(uint64_t& d, uint64_t a) {
    asm("mul.rn.f32x2 %0, %0, %1;" : "+l"(d) : "l"(a));
}
__device__ __forceinline__ void unpack2(uint64_t v, float& lo, float& hi) {
    asm("mov.b64 {%0,%1}, %2;" : "=f"(lo), "=f"(hi) : "l"(v));
}

// ---------------- wmma tf32 GEMM, cp.async double-buffered -----------------------
// C[128x128] tiles, K=768, BK=32, 256 threads (8 warps 4x2), warp tile 32x64.
#define BK 32
#define LDA 36
#define LDB 132
#define LDC 132
#define ASZ (128*LDA)            // 4608 floats per A buffer
#define BSZ (BK*LDB)             // 4224 floats per B buffer
#define SM_BYTES ((2*ASZ + 2*BSZ) * 4)   // 70656 B (epilogue stage 128*LDC=67.6KB fits)

__global__ __launch_bounds__(256, 2)
void gemm_wmma(const float* __restrict__ Ain,
               const float* __restrict__ Bq, const float* __restrict__ Bk,
               const float* __restrict__ Bv,
               const float* __restrict__ b0, const float* __restrict__ b1,
               const float* __restrict__ b2,
               float* __restrict__ outp, int mode)
{
    extern __shared__ float smem[];

    const int tid  = threadIdx.x;
    const int warp = tid >> 5;
    const int wm   = warp >> 1;
    const int wn   = warp & 1;

    const int mTile = blockIdx.y * 128;
    const int nGlob = blockIdx.x * 128;

    const float* A = (mode == 0) ? Ain : g_A;
    const float* B; const float* bias; int nTile;
    if (mode == 0) {
        const int which = nGlob / DMODEL;
        B    = (which == 0) ? Bq : (which == 1) ? Bk : Bv;
        bias = (which == 0) ? b0 : (which == 1) ? b1 : b2;
        nTile = nGlob - which*DMODEL;
    } else { B = Bq; bias = b0; nTile = nGlob; }

    wmma::fragment<wmma::accumulator, 16, 16, 8, float> c[2][4];
    #pragma unroll
    for (int i = 0; i < 2; i++)
        #pragma unroll
        for (int j = 0; j < 4; j++)
            wmma::fill_fragment(c[i][j], 0.0f);

    const int aRow = tid >> 3,  aC4 = (tid & 7) << 2;     // +32 rows per step of 256
    const int bRow = tid >> 5,  bC4 = (tid & 31) << 2;

    auto load_stage = [&](int k0, int buf) {
        float* As = smem + buf*ASZ;
        float* Bs = smem + 2*ASZ + buf*BSZ;
        #pragma unroll
        for (int t = 0; t < 4; t++) {
            const int row = aRow + t*32;
            __pipeline_memcpy_async(&As[row*LDA + aC4],
                                    &A[(size_t)(mTile + row)*DMODEL + k0 + aC4], 16);
        }
        #pragma unroll
        for (int t = 0; t < 4; t++) {
            const int row = bRow + t*8;
            __pipeline_memcpy_async(&Bs[row*LDB + bC4],
                                    &B[(size_t)(k0 + row)*DMODEL + nTile + bC4], 16);
        }
    };

    load_stage(0, 0);
    __pipeline_commit();

    for (int kc = 0; kc < DMODEL/BK; kc++) {
        const int buf = kc & 1;
        if (kc < DMODEL/BK - 1) {
            load_stage((kc+1)*BK, buf ^ 1);
            __pipeline_commit();
            __pipeline_wait_prior(1);
        } else {
            __pipeline_wait_prior(0);
        }
        __syncthreads();

        const float* As = smem + buf*ASZ;
        const float* Bs = smem + 2*ASZ + buf*BSZ;
        #pragma unroll
        for (int kk = 0; kk < BK/8; kk++) {
            wmma::fragment<wmma::matrix_a, 16, 16, 8, wmma::precision::tf32, wmma::row_major> a[2];
            wmma::fragment<wmma::matrix_b, 16, 16, 8, wmma::precision::tf32, wmma::row_major> b[4];
            #pragma unroll
            for (int i = 0; i < 2; i++) {
                wmma::load_matrix_sync(a[i], &As[(wm*32 + i*16)*LDA + kk*8], LDA);
                #pragma unroll
                for (int e = 0; e < a[i].num_elements; e++)
                    a[i].x[e] = wmma::__float_to_tf32(a[i].x[e]);
            }
            #pragma unroll
            for (int j = 0; j < 4; j++) {
                wmma::load_matrix_sync(b[j], &Bs[(kk*8)*LDB + wn*64 + j*16], LDB);
                #pragma unroll
                for (int e = 0; e < b[j].num_elements; e++)
                    b[j].x[e] = wmma::__float_to_tf32(b[j].x[e]);
            }
            #pragma unroll
            for (int i = 0; i < 2; i++)
                #pragma unroll
                for (int j = 0; j < 4; j++)
                    wmma::mma_sync(c[i][j], a[i], b[j], c[i][j]);
        }
        __syncthreads();
    }

    // stage C in smem, then coalesced bias+remap stores
    float* stage = smem;
    #pragma unroll
    for (int i = 0; i < 2; i++)
        #pragma unroll
        for (int j = 0; j < 4; j++)
            wmma::store_matrix_sync(&stage[(wm*32 + i*16)*LDC + wn*64 + j*16],
                                    c[i][j], LDC, wmma::mem_row_major);
    __syncthreads();

    if (mode == 0) {
        const int which = nGlob / DMODEL;
        float* outg = (which == 0) ? g_Q : (which == 1) ? g_K : g_V;
        #pragma unroll
        for (int t = 0; t < 16; t++) {
            const int g = tid + t*256;
            const int row = g >> 5, cc = (g & 31) << 2;
            float4 v = *(float4*)&stage[row*LDC + cc];
            const int np = nTile + cc;                 // 4-col group never straddles a head
            const int h = np / HDIM, pd = np % HDIM;
            const float4 bb = *(const float4*)&bias[np];
            v.x += bb.x; v.y += bb.y; v.z += bb.z; v.w += bb.w;
            const int m = mTile + row;
            const int b = m >> 10, s = m & 1023;
            *(float4*)&outg[(((size_t)b*NHEAD + h)*SEQ + s)*HDIM + pd] = v;
        }
    } else {
        #pragma unroll
        for (int t = 0; t < 16; t++) {
            const int g = tid + t*256;
            const int row = g >> 5, cc = (g & 31) << 2;
            float4 v = *(float4*)&stage[row*LDC + cc];
            const float4 bb = *(const float4*)&bias[nTile + cc];
            v.x += bb.x; v.y += bb.y; v.z += bb.z; v.w += bb.w;
            *(float4*)&outp[(size_t)(mTile + row)*DMODEL + nTile + cc] = v;
        }
    }
}

// ---------------- Flash attention: 128 q-rows, 32 k-cols, f32x2, conflict-free ----
#define AM 128
#define AN 32
#define QP 52                    // padded row stride (floats): 52 % 32 = 20 -> conflict-free
#define SP 36                    // sS stride
#define ATT_SMEM ((AM*QP + 2*AN*QP + AM*SP) * 4)   // 58368 B

__global__ __launch_bounds__(256)
void attn_kernel()
{
    extern __shared__ float sm[];
    float* sQ = sm;                    // [AM][QP]
    float* sK = sm + AM*QP;            // [AN][QP]
    float* sV = sK + AN*QP;            // [AN][QP]
    float* sS = sV + AN*QP;            // [AM][SP]

    const int bh = blockIdx.y;
    const int q0 = blockIdx.x * AM;
    const float* Qp = g_Q + (size_t)bh * SEQ * HDIM;
    const float* Kp = g_K + (size_t)bh * SEQ * HDIM;
    const float* Vp = g_V + (size_t)bh * SEQ * HDIM;

    const int tid = threadIdx.x;
    const int r   = tid >> 2;          // 0..63 ; rows r and r+64
    const int qd  = tid & 3;

    // load Q tile: 128 rows x 12 float4
    for (int i = tid; i < AM*12; i += 256) {
        const int row = i / 12, c4 = (i % 12) << 2;
        *(float4*)&sQ[row*QP + c4] = *(const float4*)&Qp[(size_t)(q0 + row)*HDIM + c4];
    }

    float m0 = -1e30f, m1 = -1e30f, l0 = 0.f, l1 = 0.f;
    uint64_t av[2][6];
    #pragma unroll
    for (int j = 0; j < 6; j++) { av[0][j] = 0ull; av[1][j] = 0ull; }

    const float scale = rsqrtf((float)HDIM);

    for (int kt = 0; kt < SEQ/AN; kt++) {
        __syncthreads();
        for (int i = tid; i < AN*12; i += 256) {
            const int row = i / 12, c4 = (i % 12) << 2;
            *(float4*)&sK[row*QP + c4] = *(const float4*)&Kp[(size_t)(kt*AN + row)*HDIM + c4];
            *(float4*)&sV[row*QP + c4] = *(const float4*)&Vp[(size_t)(kt*AN + row)*HDIM + c4];
        }
        __syncthreads();

        // scores: rows {r, r+64} x cols {jj*4+qd}
        uint64_t acc2[2][8];
        #pragma unroll
        for (int jj = 0; jj < 8; jj++) { acc2[0][jj] = 0ull; acc2[1][jj] = 0ull; }
        #pragma unroll
        for (int d0 = 0; d0 < HDIM; d0 += 4) {
            const ulonglong2 qa = *(const ulonglong2*)&sQ[r*QP + d0];
            const ulonglong2 qb = *(const ulonglong2*)&sQ[(r+64)*QP + d0];
            #pragma unroll
            for (int jj = 0; jj < 8; jj++) {
                const ulonglong2 k2 = *(const ulonglong2*)&sK[(jj*4 + qd)*QP + d0];
                fma2(acc2[0][jj], qa.x, k2.x);
                fma2(acc2[0][jj], qa.y, k2.y);
                fma2(acc2[1][jj], qb.x, k2.x);
                fma2(acc2[1][jj], qb.y, k2.y);
            }
        }

        #pragma unroll
        for (int row = 0; row < 2; row++) {
            float s[8], mloc = -1e30f;
            #pragma unroll
            for (int jj = 0; jj < 8; jj++) {
                float lo, hi; unpack2(acc2[row][jj], lo, hi);
                s[jj] = (lo + hi) * scale;
                mloc = fmaxf(mloc, s[jj]);
            }
            mloc = fmaxf(mloc, __shfl_xor_sync(0xffffffffu, mloc, 1));
            mloc = fmaxf(mloc, __shfl_xor_sync(0xffffffffu, mloc, 2));
            float& m_i = row ? m1 : m0;
            float& l_i = row ? l1 : l0;
            const float m_new = fmaxf(m_i, mloc);
            const float corr  = __expf(m_i - m_new);
            float lloc = 0.f;
            const int rowbase = (row ? (r+64) : r) * SP;
            #pragma unroll
            for (int jj = 0; jj < 8; jj++) {
                const float p = __expf(s[jj] - m_new);
                sS[rowbase + jj*4 + qd] = p;
                lloc += p;
            }
            lloc += __shfl_xor_sync(0xffffffffu, lloc, 1);
            lloc += __shfl_xor_sync(0xffffffffu, lloc, 2);
            l_i = l_i * corr + lloc;
            m_i = m_new;
            const uint64_t corr2 = pack2(corr);
            #pragma unroll
            for (int j = 0; j < 6; j++) mul2(av[row][j], corr2);
        }
        __syncthreads();

        // O += P @ V  : rows {r,r+64}, cols qd*12..qd*12+11
        #pragma unroll 4
        for (int n = 0; n < AN; n++) {
            const uint64_t p02 = pack2(sS[r*SP + n]);
            const uint64_t p12 = pack2(sS[(r+64)*SP + n]);
            const float* vb = &sV[n*QP + qd*12];
            const ulonglong2 v01 = *(const ulonglong2*)(vb);
            const ulonglong2 v23 = *(const ulonglong2*)(vb + 4);
            const ulonglong2 v45 = *(const ulonglong2*)(vb + 8);
            fma2(av[0][0], p02, v01.x); fma2(av[0][1], p02, v01.y);
            fma2(av[0][2], p02, v23.x); fma2(av[0][3], p02, v23.y);
            fma2(av[0][4], p02, v45.x); fma2(av[0][5], p02, v45.y);
            fma2(av[1][0], p12, v01.x); fma2(av[1][1], p12, v01.y);
            fma2(av[1][2], p12, v23.x); fma2(av[1][3], p12, v23.y);
            fma2(av[1][4], p12, v45.x); fma2(av[1][5], p12, v45.y);
        }
    }

    const int b = bh / NHEAD, h = bh % NHEAD;
    #pragma unroll
    for (int row = 0; row < 2; row++) {
        const float inv = 1.f / (row ? l1 : l0);
        float o[12];
        #pragma unroll
        for (int j = 0; j < 6; j++) {
            float lo, hi; unpack2(av[row][j], lo, hi);
            o[2*j] = lo * inv; o[2*j+1] = hi * inv;
        }
        const int mrow = q0 + (row ? (r+64) : r);
        float* op = &g_A[((size_t)b*SEQ + mrow)*DMODEL + h*HDIM + qd*12];
        *(float4*)(op)     = make_float4(o[0], o[1], o[2],  o[3]);
        *(float4*)(op + 4) = make_float4(o[4], o[5], o[6],  o[7]);
        *(float4*)(op + 8) = make_float4(o[8], o[9], o[10], o[11]);
    }
}

// ---------------- launch ---------------------------------------------------------
extern "C" void kernel_launch(void* const* d_in, const int* in_sizes, int n_in,
                              void* d_out, int out_size)
{
    const float* X  = (const float*)d_in[0];
    const float* Wq = (const float*)d_in[1];
    const float* bq = (const float*)d_in[2];
    const float* Wk = (const float*)d_in[3];
    const float* bk = (const float*)d_in[4];
    const float* Wv = (const float*)d_in[5];
    const float* bv = (const float*)d_in[6];
    const float* Wo = (const float*)d_in[7];
    const float* bo = (const float*)d_in[8];
    float* out = (float*)d_out;

    static int attr_done = 0;
    if (!attr_done) {
        cudaFuncSetAttribute(gemm_wmma, cudaFuncAttributeMaxDynamicSharedMemorySize, SM_BYTES);
        cudaFuncSetAttribute(attn_kernel, cudaFuncAttributeMaxDynamicSharedMemorySize, ATT_SMEM);
        attr_done = 1;
    }

    dim3 gQKV(3*DMODEL/128, MROWS/128);           // 18 x 64
    gemm_wmma<<<gQKV, 256, SM_BYTES>>>(X, Wq, Wk, Wv, bq, bk, bv, nullptr, 0);

    dim3 gAttn(SEQ/AM, BATCH*NHEAD);              // 8 x 128
    attn_kernel<<<gAttn, 256, ATT_SMEM>>>();

    dim3 gO(DMODEL/128, MROWS/128);               // 6 x 64
    gemm_wmma<<<gO, 256, SM_BYTES>>>(X, Wo, nullptr, nullptr, bo, nullptr, nullptr, out, 1);
}

// round 8
// speedup vs baseline: 5.1737x; 1.7556x over previous
#include <cuda_runtime.h>
#include <cuda_pipeline.h>
#include <mma.h>
#include <cstdint>
#include <math.h>

using namespace nvcuda;

#define BATCH 8
#define SEQ 1024
#define DMODEL 768
#define NHEAD 16
#define HDIM 48
#define MROWS (BATCH*SEQ)

// ---------------- scratch (allocation-free rule: device globals) -----------------
__device__ float g_Q[MROWS*DMODEL];        // [B,H,S,PD] tf32-rounded
__device__ float g_K[MROWS*DMODEL];        // [B,H,S,PD] tf32-rounded
__device__ float g_V[MROWS*DMODEL];        // [B,H,S,PD] tf32-rounded
__device__ float g_A[MROWS*DMODEL];        // [B,S,D]   tf32-rounded
__device__ float g_Xr[MROWS*DMODEL];       // X tf32-rounded
__device__ float g_Wr[3*DMODEL*DMODEL];    // Wq,Wk,Wv tf32-rounded
__device__ float g_WoR[DMODEL*DMODEL];     // Wo tf32-rounded

// ---------------- helpers ---------------------------------------------------------
__device__ __forceinline__ float tf32r(float x) {
    uint32_t r; asm("cvt.rna.tf32.f32 %0, %1;" : "=r"(r) : "f"(x));
    return __uint_as_float(r);
}
__device__ __forceinline__ void mma8(float& c0, float& c1, float& c2, float& c3,
                                     uint32_t a0, uint32_t a1, uint32_t a2, uint32_t a3,
                                     uint32_t b0, uint32_t b1) {
    asm volatile("mma.sync.aligned.m16n8k8.row.col.f32.tf32.tf32.f32 "
                 "{%0,%1,%2,%3}, {%4,%5,%6,%7}, {%8,%9}, {%0,%1,%2,%3};"
                 : "+f"(c0), "+f"(c1), "+f"(c2), "+f"(c3)
                 : "r"(a0), "r"(a1), "r"(a2), "r"(a3), "r"(b0), "r"(b1));
}

// ---------------- tf32 pre-rounding copy ------------------------------------------
__global__ __launch_bounds__(256)
void round4_copy(const float* __restrict__ src, float* __restrict__ dst, int n4)
{
    const int i = blockIdx.x*256 + threadIdx.x;
    if (i < n4) {
        float4 v = ((const float4*)src)[i];
        v.x = tf32r(v.x); v.y = tf32r(v.y); v.z = tf32r(v.z); v.w = tf32r(v.w);
        ((float4*)dst)[i] = v;
    }
}

// ---------------- wmma tf32 GEMM, cp.async double-buffered (pre-rounded inputs) ---
#define BK 32
#define LDA 36
#define LDB 132
#define LDC 132
#define ASZ (128*LDA)
#define BSZ (BK*LDB)
#define SM_BYTES ((2*ASZ + 2*BSZ) * 4)

__global__ __launch_bounds__(256, 2)
void gemm_wmma(const float* __restrict__ b0, const float* __restrict__ b1,
               const float* __restrict__ b2, float* __restrict__ outp, int mode)
{
    extern __shared__ float smem[];

    const int tid  = threadIdx.x;
    const int warp = tid >> 5;
    const int wm   = warp >> 1;
    const int wn   = warp & 1;

    const int mTile = blockIdx.y * 128;
    const int nGlob = blockIdx.x * 128;

    const float* A; const float* B; const float* bias; int nTile;
    if (mode == 0) {
        const int which = nGlob / DMODEL;
        A    = g_Xr;
        B    = g_Wr + (size_t)which*DMODEL*DMODEL;
        bias = (which == 0) ? b0 : (which == 1) ? b1 : b2;
        nTile = nGlob - which*DMODEL;
    } else { A = g_A; B = g_WoR; bias = b0; nTile = nGlob; }

    wmma::fragment<wmma::accumulator, 16, 16, 8, float> c[2][4];
    #pragma unroll
    for (int i = 0; i < 2; i++)
        #pragma unroll
        for (int j = 0; j < 4; j++)
            wmma::fill_fragment(c[i][j], 0.0f);

    const int aRow = tid >> 3,  aC4 = (tid & 7) << 2;
    const int bRow = tid >> 5,  bC4 = (tid & 31) << 2;

    auto load_stage = [&](int k0, int buf) {
        float* As = smem + buf*ASZ;
        float* Bs = smem + 2*ASZ + buf*BSZ;
        #pragma unroll
        for (int t = 0; t < 4; t++) {
            const int row = aRow + t*32;
            __pipeline_memcpy_async(&As[row*LDA + aC4],
                                    &A[(size_t)(mTile + row)*DMODEL + k0 + aC4], 16);
        }
        #pragma unroll
        for (int t = 0; t < 4; t++) {
            const int row = bRow + t*8;
            __pipeline_memcpy_async(&Bs[row*LDB + bC4],
                                    &B[(size_t)(k0 + row)*DMODEL + nTile + bC4], 16);
        }
    };

    load_stage(0, 0);
    __pipeline_commit();

    for (int kc = 0; kc < DMODEL/BK; kc++) {
        const int buf = kc & 1;
        if (kc < DMODEL/BK - 1) {
            load_stage((kc+1)*BK, buf ^ 1);
            __pipeline_commit();
            __pipeline_wait_prior(1);
        } else {
            __pipeline_wait_prior(0);
        }
        __syncthreads();

        const float* As = smem + buf*ASZ;
        const float* Bs = smem + 2*ASZ + buf*BSZ;
        #pragma unroll
        for (int kk = 0; kk < BK/8; kk++) {
            wmma::fragment<wmma::matrix_a, 16, 16, 8, wmma::precision::tf32, wmma::row_major> a[2];
            wmma::fragment<wmma::matrix_b, 16, 16, 8, wmma::precision::tf32, wmma::row_major> b[4];
            #pragma unroll
            for (int i = 0; i < 2; i++)
                wmma::load_matrix_sync(a[i], &As[(wm*32 + i*16)*LDA + kk*8], LDA);
            #pragma unroll
            for (int j = 0; j < 4; j++)
                wmma::load_matrix_sync(b[j], &Bs[(kk*8)*LDB + wn*64 + j*16], LDB);
            #pragma unroll
            for (int i = 0; i < 2; i++)
                #pragma unroll
                for (int j = 0; j < 4; j++)
                    wmma::mma_sync(c[i][j], a[i], b[j], c[i][j]);
        }
        __syncthreads();
    }

    float* stage = smem;
    #pragma unroll
    for (int i = 0; i < 2; i++)
        #pragma unroll
        for (int j = 0; j < 4; j++)
            wmma::store_matrix_sync(&stage[(wm*32 + i*16)*LDC + wn*64 + j*16],
                                    c[i][j], LDC, wmma::mem_row_major);
    __syncthreads();

    if (mode == 0) {
        const int which = nGlob / DMODEL;
        float* outg = (which == 0) ? g_Q : (which == 1) ? g_K : g_V;
        #pragma unroll
        for (int t = 0; t < 16; t++) {
            const int g = tid + t*256;
            const int row = g >> 5, cc = (g & 31) << 2;
            float4 v = *(float4*)&stage[row*LDC + cc];
            const int np = nTile + cc;
            const int h = np / HDIM, pd = np % HDIM;
            const float4 bb = *(const float4*)&bias[np];
            v.x = tf32r(v.x + bb.x); v.y = tf32r(v.y + bb.y);
            v.z = tf32r(v.z + bb.z); v.w = tf32r(v.w + bb.w);
            const int m = mTile + row;
            const int b = m >> 10, s = m & 1023;
            *(float4*)&outg[(((size_t)b*NHEAD + h)*SEQ + s)*HDIM + pd] = v;
        }
    } else {
        #pragma unroll
        for (int t = 0; t < 16; t++) {
            const int g = tid + t*256;
            const int row = g >> 5, cc = (g & 31) << 2;
            float4 v = *(float4*)&stage[row*LDC + cc];
            const float4 bb = *(const float4*)&bias[nTile + cc];
            v.x += bb.x; v.y += bb.y; v.z += bb.z; v.w += bb.w;
            *(float4*)&outp[(size_t)(mTile + row)*DMODEL + nTile + cc] = v;
        }
    }
}

// ---------------- Flash attention on mma.sync m16n8k8 tf32 ------------------------
// CTA: 256 thr (8 warps), 128 q-rows; warp w owns rows 16w..16w+15.
// KT=64 k-cols per iter. O accum register-resident with per-row rescale.
#define KT 64
#define QS 52   // 52%32=20 -> Q/K frag LDS conflict-free
#define VS 56   // 56%32=24 -> V frag LDS conflict-free
#define PS 68   // 68%32=4  -> P frag LDS conflict-free
#define ATT_SMEM ((128*QS + KT*QS + KT*VS + 128*PS) * 4)   // 89088 B

__global__ __launch_bounds__(256, 2)
void attn_mma()
{
    extern __shared__ float sm[];
    float* sQ = sm;                 // [128][QS]
    float* sK = sQ + 128*QS;        // [KT][QS]
    float* sV = sK + KT*QS;         // [KT][VS]
    float* sP = sV + KT*VS;         // [128][PS]

    const int bh = blockIdx.y;
    const int q0 = blockIdx.x * 128;
    const float* Qp = g_Q + (size_t)bh * SEQ * HDIM;
    const float* Kp = g_K + (size_t)bh * SEQ * HDIM;
    const float* Vp = g_V + (size_t)bh * SEQ * HDIM;

    const int tid  = threadIdx.x;
    const int w    = tid >> 5, lane = tid & 31;
    const int g    = lane >> 2, t = lane & 3;
    const int wr   = w * 16;

    for (int i = tid; i < 128*12; i += 256) {
        const int row = i / 12, c4 = (i % 12) << 2;
        *(float4*)&sQ[row*QS + c4] = *(const float4*)&Qp[(size_t)(q0 + row)*HDIM + c4];
    }
    __syncthreads();

    // Q A-fragments, persistent (rows wr+g / wr+g+8, k-chunks of 8)
    uint32_t qa[6][4];
    #pragma unroll
    for (int kc = 0; kc < 6; kc++) {
        qa[kc][0] = __float_as_uint(sQ[(wr+g  )*QS + kc*8 + t    ]);
        qa[kc][1] = __float_as_uint(sQ[(wr+g+8)*QS + kc*8 + t    ]);
        qa[kc][2] = __float_as_uint(sQ[(wr+g  )*QS + kc*8 + t + 4]);
        qa[kc][3] = __float_as_uint(sQ[(wr+g+8)*QS + kc*8 + t + 4]);
    }

    float m_lo = -1e30f, m_hi = -1e30f, l_lo = 0.f, l_hi = 0.f;
    float o[6][4];
    #pragma unroll
    for (int n = 0; n < 6; n++)
        { o[n][0]=0.f; o[n][1]=0.f; o[n][2]=0.f; o[n][3]=0.f; }

    const float scale = rsqrtf((float)HDIM);

    for (int kt = 0; kt < SEQ/KT; kt++) {
        __syncthreads();
        for (int i = tid; i < KT*12; i += 256) {
            const int row = i / 12, c4 = (i % 12) << 2;
            *(float4*)&sK[row*QS + c4] = *(const float4*)&Kp[(size_t)(kt*KT + row)*HDIM + c4];
            *(float4*)&sV[row*VS + c4] = *(const float4*)&Vp[(size_t)(kt*KT + row)*HDIM + c4];
        }
        __syncthreads();

        // scores S = Q K^T : 16x64 per warp, 8 n-frags
        float s[8][4];
        #pragma unroll
        for (int nf = 0; nf < 8; nf++) {
            float c0 = 0.f, c1 = 0.f, c2 = 0.f, c3 = 0.f;
            #pragma unroll
            for (int kc = 0; kc < 6; kc++) {
                const uint32_t b0 = __float_as_uint(sK[(nf*8+g)*QS + kc*8 + t    ]);
                const uint32_t b1 = __float_as_uint(sK[(nf*8+g)*QS + kc*8 + t + 4]);
                mma8(c0, c1, c2, c3, qa[kc][0], qa[kc][1], qa[kc][2], qa[kc][3], b0, b1);
            }
            s[nf][0] = c0*scale; s[nf][1] = c1*scale;
            s[nf][2] = c2*scale; s[nf][3] = c3*scale;
        }

        // online softmax (rows wr+g and wr+g+8)
        float mx0 = -1e30f, mx1 = -1e30f;
        #pragma unroll
        for (int nf = 0; nf < 8; nf++) {
            mx0 = fmaxf(mx0, fmaxf(s[nf][0], s[nf][1]));
            mx1 = fmaxf(mx1, fmaxf(s[nf][2], s[nf][3]));
        }
        mx0 = fmaxf(mx0, __shfl_xor_sync(0xffffffffu, mx0, 1));
        mx0 = fmaxf(mx0, __shfl_xor_sync(0xffffffffu, mx0, 2));
        mx1 = fmaxf(mx1, __shfl_xor_sync(0xffffffffu, mx1, 1));
        mx1 = fmaxf(mx1, __shfl_xor_sync(0xffffffffu, mx1, 2));
        const float mn0 = fmaxf(m_lo, mx0), mn1 = fmaxf(m_hi, mx1);
        const float cr0 = __expf(m_lo - mn0), cr1 = __expf(m_hi - mn1);
        m_lo = mn0; m_hi = mn1;

        float sum0 = 0.f, sum1 = 0.f;
        #pragma unroll
        for (int nf = 0; nf < 8; nf++) {
            const float p0 = __expf(s[nf][0] - mn0);
            const float p1 = __expf(s[nf][1] - mn0);
            const float p2 = __expf(s[nf][2] - mn1);
            const float p3 = __expf(s[nf][3] - mn1);
            sum0 += p0 + p1; sum1 += p2 + p3;
            *(float2*)&sP[(wr+g  )*PS + nf*8 + 2*t] = make_float2(tf32r(p0), tf32r(p1));
            *(float2*)&sP[(wr+g+8)*PS + nf*8 + 2*t] = make_float2(tf32r(p2), tf32r(p3));
        }
        sum0 += __shfl_xor_sync(0xffffffffu, sum0, 1);
        sum0 += __shfl_xor_sync(0xffffffffu, sum0, 2);
        sum1 += __shfl_xor_sync(0xffffffffu, sum1, 1);
        sum1 += __shfl_xor_sync(0xffffffffu, sum1, 2);
        l_lo = l_lo*cr0 + sum0;
        l_hi = l_hi*cr1 + sum1;
        #pragma unroll
        for (int n = 0; n < 6; n++) {
            o[n][0] *= cr0; o[n][1] *= cr0;
            o[n][2] *= cr1; o[n][3] *= cr1;
        }
        __syncwarp();

        // O += P V : A = P [16x64], B = V [64x48]
        #pragma unroll
        for (int kc = 0; kc < 8; kc++) {
            const uint32_t pa0 = __float_as_uint(sP[(wr+g  )*PS + kc*8 + t    ]);
            const uint32_t pa1 = __float_as_uint(sP[(wr+g+8)*PS + kc*8 + t    ]);
            const uint32_t pa2 = __float_as_uint(sP[(wr+g  )*PS + kc*8 + t + 4]);
            const uint32_t pa3 = __float_as_uint(sP[(wr+g+8)*PS + kc*8 + t + 4]);
            #pragma unroll
            for (int nf = 0; nf < 6; nf++) {
                const uint32_t b0 = __float_as_uint(sV[(kc*8 + t    )*VS + nf*8 + g]);
                const uint32_t b1 = __float_as_uint(sV[(kc*8 + t + 4)*VS + nf*8 + g]);
                mma8(o[nf][0], o[nf][1], o[nf][2], o[nf][3], pa0, pa1, pa2, pa3, b0, b1);
            }
        }
    }

    // epilogue -> g_A [B,S,D], tf32-rounded for the O-projection
    const int b = bh >> 4, h = bh & 15;
    const float inv0 = 1.f / l_lo, inv1 = 1.f / l_hi;
    const int m0r = q0 + wr + g, m1r = m0r + 8;
    #pragma unroll
    for (int nf = 0; nf < 6; nf++) {
        const int col = h*HDIM + nf*8 + 2*t;
        *(float2*)&g_A[((size_t)b*SEQ + m0r)*DMODEL + col] =
            make_float2(tf32r(o[nf][0]*inv0), tf32r(o[nf][1]*inv0));
        *(float2*)&g_A[((size_t)b*SEQ + m1r)*DMODEL + col] =
            make_float2(tf32r(o[nf][2]*inv1), tf32r(o[nf][3]*inv1));
    }
}

// ---------------- launch ----------------------------------------------------------
extern "C" void kernel_launch(void* const* d_in, const int* in_sizes, int n_in,
                              void* d_out, int out_size)
{
    const float* X  = (const float*)d_in[0];
    const float* Wq = (const float*)d_in[1];
    const float* bq = (const float*)d_in[2];
    const float* Wk = (const float*)d_in[3];
    const float* bk = (const float*)d_in[4];
    const float* Wv = (const float*)d_in[5];
    const float* bv = (const float*)d_in[6];
    const float* Wo = (const float*)d_in[7];
    const float* bo = (const float*)d_in[8];
    float* out = (float*)d_out;

    static int attr_done = 0;
    if (!attr_done) {
        cudaFuncSetAttribute(gemm_wmma, cudaFuncAttributeMaxDynamicSharedMemorySize, SM_BYTES);
        cudaFuncSetAttribute(attn_mma, cudaFuncAttributeMaxDynamicSharedMemorySize, ATT_SMEM);
        attr_done = 1;
    }

    float *g_Xr_p, *g_Wr_p, *g_WoR_p;
    cudaGetSymbolAddress((void**)&g_Xr_p, g_Xr);
    cudaGetSymbolAddress((void**)&g_Wr_p, g_Wr);
    cudaGetSymbolAddress((void**)&g_WoR_p, g_WoR);

    const int nX4 = MROWS*DMODEL/4;              // 1572864
    const int nW4 = DMODEL*DMODEL/4;             // 147456
    round4_copy<<<(nX4+255)/256, 256>>>(X,  g_Xr_p, nX4);
    round4_copy<<<(nW4+255)/256, 256>>>(Wq, g_Wr_p,            nW4);
    round4_copy<<<(nW4+255)/256, 256>>>(Wk, g_Wr_p +   nW4*4,  nW4);
    round4_copy<<<(nW4+255)/256, 256>>>(Wv, g_Wr_p + 2*nW4*4,  nW4);
    round4_copy<<<(nW4+255)/256, 256>>>(Wo, g_WoR_p, nW4);

    dim3 gQKV(3*DMODEL/128, MROWS/128);          // 18 x 64
    gemm_wmma<<<gQKV, 256, SM_BYTES>>>(bq, bk, bv, nullptr, 0);

    dim3 gAttn(SEQ/128, BATCH*NHEAD);            // 8 x 128
    attn_mma<<<gAttn, 256, ATT_SMEM>>>();

    dim3 gO(DMODEL/128, MROWS/128);              // 6 x 64
    gemm_wmma<<<gO, 256, SM_BYTES>>>(bo, nullptr, nullptr, out, 1);
}

// round 15
// speedup vs baseline: 7.0795x; 1.3684x over previous
#include <cuda_runtime.h>
#include <cuda_pipeline.h>
#include <cstdint>
#include <math.h>

#define BATCH 8
#define SEQ 1024
#define DMODEL 768
#define NHEAD 16
#define HDIM 48
#define MROWS (BATCH*SEQ)

// ---------------- scratch (allocation-free rule: device globals) -----------------
__device__ float g_Q[MROWS*DMODEL];        // [B,H,S,PD] tf32-rounded
__device__ float g_K[MROWS*DMODEL];        // [B,H,S,PD] tf32-rounded
__device__ float g_V[MROWS*DMODEL];        // [B,H,S,PD] tf32-rounded
__device__ float g_A[MROWS*DMODEL];        // [B,S,D]   tf32-rounded
__device__ float g_Xr[MROWS*DMODEL];       // X tf32-rounded
__device__ float g_Wr[3*DMODEL*DMODEL];    // Wq,Wk,Wv tf32-rounded
__device__ float g_WoR[DMODEL*DMODEL];     // Wo tf32-rounded

// ---------------- helpers ---------------------------------------------------------
__device__ __forceinline__ float tf32r(float x) {
    uint32_t r; asm("cvt.rna.tf32.f32 %0, %1;" : "=r"(r) : "f"(x));
    return __uint_as_float(r);
}
__device__ __forceinline__ void mma8(float& c0, float& c1, float& c2, float& c3,
                                     uint32_t a0, uint32_t a1, uint32_t a2, uint32_t a3,
                                     uint32_t b0, uint32_t b1) {
    asm volatile("mma.sync.aligned.m16n8k8.row.col.f32.tf32.tf32.f32 "
                 "{%0,%1,%2,%3}, {%4,%5,%6,%7}, {%8,%9}, {%0,%1,%2,%3};"
                 : "+f"(c0), "+f"(c1), "+f"(c2), "+f"(c3)
                 : "r"(a0), "r"(a1), "r"(a2), "r"(a3), "r"(b0), "r"(b1));
}

// ---------------- fused tf32 pre-rounding (X, Wq, Wk, Wv, Wo in one launch) -------
#define NX4 (MROWS*DMODEL/4)
#define NW4 (DMODEL*DMODEL/4)
#define NTOT4 (NX4 + 4*NW4)

__global__ __launch_bounds__(256)
void round_all(const float* __restrict__ X,  const float* __restrict__ Wq,
               const float* __restrict__ Wk, const float* __restrict__ Wv,
               const float* __restrict__ Wo)
{
    const int i = blockIdx.x*256 + threadIdx.x;
    if (i >= NTOT4) return;
    const float4* src; float4* dst; int off;
    if (i < NX4) { src = (const float4*)X; dst = (float4*)g_Xr; off = i; }
    else {
        const int j = i - NX4, which = j / NW4; off = j - which*NW4;
        src = (const float4*)((which == 0) ? Wq : (which == 1) ? Wk :
                              (which == 2) ? Wv : Wo);
        dst = (which < 3) ? (float4*)(g_Wr + (size_t)which*DMODEL*DMODEL)
                          : (float4*)g_WoR;
    }
    float4 v = src[off];
    v.x = tf32r(v.x); v.y = tf32r(v.y); v.z = tf32r(v.z); v.w = tf32r(v.w);
    dst[off] = v;
}

// ---------------- manual mma GEMM: 128x128 CTA, 4 warps of 64x64, BK=32 -----------
#define BK 32
#define LDA 36     // A-frag bank = 4g+t  (36%32=4)  conflict-free
#define LDB 136    // B-frag bank = 8t+g  (136%32=8) conflict-free
#define LDC 132
#define ASZ (128*LDA)
#define BSZ (BK*LDB)
#define SM_BYTES ((2*ASZ + 2*BSZ) * 4)   // 71680 B ; epilogue stage 128*LDC*4=67584 fits

__global__ __launch_bounds__(128, 2)
void gemm_mma(const float* __restrict__ b0p, const float* __restrict__ b1p,
              const float* __restrict__ b2p, float* __restrict__ outp, int mode)
{
    extern __shared__ float smem[];

    const int tid  = threadIdx.x;
    const int warp = tid >> 5, lane = tid & 31;
    const int g    = lane >> 2, t = lane & 3;
    const int wm   = warp >> 1, wn = warp & 1;

    const int mTile = blockIdx.y * 128;
    const int nGlob = blockIdx.x * 128;

    const float* A; const float* B; const float* bias; int nTile;
    if (mode == 0) {
        const int which = nGlob / DMODEL;
        A    = g_Xr;
        B    = g_Wr + (size_t)which*DMODEL*DMODEL;
        bias = (which == 0) ? b0p : (which == 1) ? b1p : b2p;
        nTile = nGlob - which*DMODEL;
    } else { A = g_A; B = g_WoR; bias = b0p; nTile = nGlob; }

    float c[4][8][4];
    #pragma unroll
    for (int mi = 0; mi < 4; mi++)
        #pragma unroll
        for (int ni = 0; ni < 8; ni++)
            { c[mi][ni][0]=0.f; c[mi][ni][1]=0.f; c[mi][ni][2]=0.f; c[mi][ni][3]=0.f; }

    auto load_stage = [&](int k0, int buf) {
        float* As = smem + buf*ASZ;
        float* Bs = smem + 2*ASZ + buf*BSZ;
        #pragma unroll
        for (int i = 0; i < 8; i++) {           // A: 128x32 = 1024 float4
            const int idx = tid + i*128;
            const int row = idx >> 3, c4 = (idx & 7) << 2;
            __pipeline_memcpy_async(&As[row*LDA + c4],
                                    &A[(size_t)(mTile + row)*DMODEL + k0 + c4], 16);
        }
        #pragma unroll
        for (int i = 0; i < 8; i++) {           // B: 32x128 = 1024 float4
            const int idx = tid + i*128;
            const int row = idx >> 5, c4 = (idx & 31) << 2;
            __pipeline_memcpy_async(&Bs[row*LDB + c4],
                                    &B[(size_t)(k0 + row)*DMODEL + nTile + c4], 16);
        }
    };

    load_stage(0, 0);
    __pipeline_commit();

    for (int kc = 0; kc < DMODEL/BK; kc++) {
        const int buf = kc & 1;
        if (kc < DMODEL/BK - 1) {
            load_stage((kc+1)*BK, buf ^ 1);
            __pipeline_commit();
            __pipeline_wait_prior(1);
        } else {
            __pipeline_wait_prior(0);
        }
        __syncthreads();

        const float* As = smem + buf*ASZ;
        const float* Bs = smem + 2*ASZ + buf*BSZ;
        #pragma unroll
        for (int kk = 0; kk < BK/8; kk++) {
            uint32_t a[4][4], b[8][2];
            #pragma unroll
            for (int mi = 0; mi < 4; mi++) {
                const float* ar = &As[(wm*64 + mi*16)*LDA + kk*8];
                a[mi][0] = __float_as_uint(ar[(g    )*LDA + t    ]);
                a[mi][1] = __float_as_uint(ar[(g + 8)*LDA + t    ]);
                a[mi][2] = __float_as_uint(ar[(g    )*LDA + t + 4]);
                a[mi][3] = __float_as_uint(ar[(g + 8)*LDA + t + 4]);
            }
            #pragma unroll
            for (int ni = 0; ni < 8; ni++) {
                const float* br = &Bs[kk*8*LDB + wn*64 + ni*8 + g];
                b[ni][0] = __float_as_uint(br[ t     *LDB]);
                b[ni][1] = __float_as_uint(br[(t + 4)*LDB]);
            }
            #pragma unroll
            for (int mi = 0; mi < 4; mi++)
                #pragma unroll
                for (int ni = 0; ni < 8; ni++)
                    mma8(c[mi][ni][0], c[mi][ni][1], c[mi][ni][2], c[mi][ni][3],
                         a[mi][0], a[mi][1], a[mi][2], a[mi][3],
                         b[ni][0], b[ni][1]);
        }
        __syncthreads();
    }

    // stage accum -> smem, then coalesced remap stores
    float* stage = smem;
    #pragma unroll
    for (int mi = 0; mi < 4; mi++)
        #pragma unroll
        for (int ni = 0; ni < 8; ni++) {
            const int col = wn*64 + ni*8 + 2*t;
            *(float2*)&stage[(wm*64 + mi*16 + g    )*LDC + col] =
                make_float2(c[mi][ni][0], c[mi][ni][1]);
            *(float2*)&stage[(wm*64 + mi*16 + g + 8)*LDC + col] =
                make_float2(c[mi][ni][2], c[mi][ni][3]);
        }
    __syncthreads();

    if (mode == 0) {
        const int which = nGlob / DMODEL;
        float* outg = (which == 0) ? g_Q : (which == 1) ? g_K : g_V;
        #pragma unroll
        for (int it = 0; it < 32; it++) {
            const int gg = tid + it*128;
            const int row = gg >> 5, cc = (gg & 31) << 2;
            float4 v = *(float4*)&stage[row*LDC + cc];
            const int np = nTile + cc;
            const int h = np / HDIM, pd = np % HDIM;
            const float4 bb = *(const float4*)&bias[np];
            v.x = tf32r(v.x + bb.x); v.y = tf32r(v.y + bb.y);
            v.z = tf32r(v.z + bb.z); v.w = tf32r(v.w + bb.w);
            const int m = mTile + row;
            const int b = m >> 10, s = m & 1023;
            *(float4*)&outg[(((size_t)b*NHEAD + h)*SEQ + s)*HDIM + pd] = v;
        }
    } else {
        #pragma unroll
        for (int it = 0; it < 32; it++) {
            const int gg = tid + it*128;
            const int row = gg >> 5, cc = (gg & 31) << 2;
            float4 v = *(float4*)&stage[row*LDC + cc];
            const float4 bb = *(const float4*)&bias[nTile + cc];
            v.x += bb.x; v.y += bb.y; v.z += bb.z; v.w += bb.w;
            *(float4*)&outp[(size_t)(mTile + row)*DMODEL + nTile + cc] = v;
        }
    }
}

// ---------------- Flash attention: 4 warps x 32 rows, shuffle P->A-frag -----------
#define KT 32
#define QS 52    // K/Q frag bank = 4g+t   conflict-free
#define VS 56    // V row = 48 floats + pad; V frag bank = 24t+g  conflict-free
#define ATT_SMEM ((128*QS + KT*QS + KT*VS) * 4)   // 40448 B

__global__ __launch_bounds__(128, 2)
void attn_mma()
{
    extern __shared__ float sm[];
    float* sQ = sm;               // [128][QS]
    float* sK = sQ + 128*QS;      // [KT][QS]
    float* sV = sK + KT*QS;       // [KT][VS]

    const int bh = blockIdx.y;
    const int q0 = blockIdx.x * 128;
    const float* Qp = g_Q + (size_t)bh * SEQ * HDIM;
    const float* Kp = g_K + (size_t)bh * SEQ * HDIM;
    const float* Vp = g_V + (size_t)bh * SEQ * HDIM;

    const int tid  = threadIdx.x;
    const int w    = tid >> 5, lane = tid & 31;
    const int g    = lane >> 2, t = lane & 3;
    const int wr   = w * 32;

    for (int i = tid; i < 128*12; i += 128) {
        const int row = i / 12, c4 = (i % 12) << 2;
        *(float4*)&sQ[row*QS + c4] = *(const float4*)&Qp[(size_t)(q0 + row)*HDIM + c4];
    }
    __syncthreads();

    // persistent Q A-fragments: 2 m16-frags (rows wr..wr+31), 6 k-chunks
    uint32_t qa[2][6][4];
    #pragma unroll
    for (int mi = 0; mi < 2; mi++)
        #pragma unroll
        for (int kc = 0; kc < 6; kc++) {
            const float* qr = &sQ[(wr + mi*16)*QS + kc*8];
            qa[mi][kc][0] = __float_as_uint(qr[(g    )*QS + t    ]);
            qa[mi][kc][1] = __float_as_uint(qr[(g + 8)*QS + t    ]);
            qa[mi][kc][2] = __float_as_uint(qr[(g    )*QS + t + 4]);
            qa[mi][kc][3] = __float_as_uint(qr[(g + 8)*QS + t + 4]);
        }

    float mrow[4], lrow[4];
    #pragma unroll
    for (int i = 0; i < 4; i++) { mrow[i] = -1e30f; lrow[i] = 0.f; }
    float o[2][6][4];
    #pragma unroll
    for (int mi = 0; mi < 2; mi++)
        #pragma unroll
        for (int vn = 0; vn < 6; vn++)
            { o[mi][vn][0]=0.f; o[mi][vn][1]=0.f; o[mi][vn][2]=0.f; o[mi][vn][3]=0.f; }

    const float scale = rsqrtf((float)HDIM);

    for (int kt = 0; kt < SEQ/KT; kt++) {
        __syncthreads();
        for (int i = tid; i < KT*12; i += 128) {
            const int row = i / 12, c4 = (i % 12) << 2;
            *(float4*)&sK[row*QS + c4] = *(const float4*)&Kp[(size_t)(kt*KT + row)*HDIM + c4];
            *(float4*)&sV[row*VS + c4] = *(const float4*)&Vp[(size_t)(kt*KT + row)*HDIM + c4];
        }
        __syncthreads();

        // S = Q K^T : 32x32 per warp -> s[2][4][4]
        float s[2][4][4];
        #pragma unroll
        for (int mi = 0; mi < 2; mi++)
            #pragma unroll
            for (int nf = 0; nf < 4; nf++)
                { s[mi][nf][0]=0.f; s[mi][nf][1]=0.f; s[mi][nf][2]=0.f; s[mi][nf][3]=0.f; }
        #pragma unroll
        for (int kc = 0; kc < 6; kc++)
            #pragma unroll
            for (int nf = 0; nf < 4; nf++) {
                const uint32_t b0 = __float_as_uint(sK[(nf*8 + g)*QS + kc*8 + t    ]);
                const uint32_t b1 = __float_as_uint(sK[(nf*8 + g)*QS + kc*8 + t + 4]);
                #pragma unroll
                for (int mi = 0; mi < 2; mi++)
                    mma8(s[mi][nf][0], s[mi][nf][1], s[mi][nf][2], s[mi][nf][3],
                         qa[mi][kc][0], qa[mi][kc][1], qa[mi][kc][2], qa[mi][kc][3],
                         b0, b1);
            }

        // online softmax over 4 row-groups: rows wr+g + {0,8,16,24}
        #pragma unroll
        for (int ri = 0; ri < 4; ri++) {
            const int mi = ri >> 1, hh = (ri & 1) * 2;   // regs hh, hh+1
            float mx = -1e30f;
            #pragma unroll
            for (int nf = 0; nf < 4; nf++) {
                s[mi][nf][hh]   *= scale;
                s[mi][nf][hh+1] *= scale;
                mx = fmaxf(mx, fmaxf(s[mi][nf][hh], s[mi][nf][hh+1]));
            }
            mx = fmaxf(mx, __shfl_xor_sync(0xffffffffu, mx, 1));
            mx = fmaxf(mx, __shfl_xor_sync(0xffffffffu, mx, 2));
            const float mn = fmaxf(mrow[ri], mx);
            const float cr = __expf(mrow[ri] - mn);
            mrow[ri] = mn;
            float sum = 0.f;
            #pragma unroll
            for (int nf = 0; nf < 4; nf++) {
                const float p0 = __expf(s[mi][nf][hh]   - mn);
                const float p1 = __expf(s[mi][nf][hh+1] - mn);
                sum += p0 + p1;
                s[mi][nf][hh]   = tf32r(p0);
                s[mi][nf][hh+1] = tf32r(p1);
            }
            sum += __shfl_xor_sync(0xffffffffu, sum, 1);
            sum += __shfl_xor_sync(0xffffffffu, sum, 2);
            lrow[ri] = lrow[ri]*cr + sum;
            #pragma unroll
            for (int vn = 0; vn < 6; vn++) {
                o[mi][vn][hh]   *= cr;
                o[mi][vn][hh+1] *= cr;
            }
        }

        // O += P V : convert S-frag -> A-frag via shfl (no smem round trip)
        const int L1 = 4*g + (t >> 1);
        const int L2 = L1 + 2;
        const bool odd = (t & 1);
        #pragma unroll
        for (int nf = 0; nf < 4; nf++) {          // nf = k8 chunk of PV
            #pragma unroll
            for (int mi = 0; mi < 2; mi++) {
                const float e0 = __shfl_sync(0xffffffffu, s[mi][nf][0], L1);
                const float o0 = __shfl_sync(0xffffffffu, s[mi][nf][1], L1);
                const float e1 = __shfl_sync(0xffffffffu, s[mi][nf][2], L1);
                const float o1 = __shfl_sync(0xffffffffu, s[mi][nf][3], L1);
                const float e2 = __shfl_sync(0xffffffffu, s[mi][nf][0], L2);
                const float o2 = __shfl_sync(0xffffffffu, s[mi][nf][1], L2);
                const float e3 = __shfl_sync(0xffffffffu, s[mi][nf][2], L2);
                const float o3 = __shfl_sync(0xffffffffu, s[mi][nf][3], L2);
                const uint32_t a0 = __float_as_uint(odd ? o0 : e0);
                const uint32_t a1 = __float_as_uint(odd ? o1 : e1);
                const uint32_t a2 = __float_as_uint(odd ? o2 : e2);
                const uint32_t a3 = __float_as_uint(odd ? o3 : e3);
                #pragma unroll
                for (int vn = 0; vn < 6; vn++) {
                    const uint32_t b0 = __float_as_uint(sV[(nf*8 + t    )*VS + vn*8 + g]);
                    const uint32_t b1 = __float_as_uint(sV[(nf*8 + t + 4)*VS + vn*8 + g]);
                    mma8(o[mi][vn][0], o[mi][vn][1], o[mi][vn][2], o[mi][vn][3],
                         a0, a1, a2, a3, b0, b1);
                }
            }
        }
    }

    // epilogue -> g_A [B,S,D], tf32-rounded for the O-projection
    const int b = bh >> 4, h = bh & 15;
    const float inv0 = 1.f / lrow[0], inv1 = 1.f / lrow[1];
    const float inv2 = 1.f / lrow[2], inv3 = 1.f / lrow[3];
    #pragma unroll
    for (int mi = 0; mi < 2; mi++) {
        const int r0 = q0 + wr + mi*16 + g;
        const float iA = mi ? inv2 : inv0;
        const float iB = mi ? inv3 : inv1;
        #pragma unroll
        for (int vn = 0; vn < 6; vn++) {
            const int col = h*HDIM + vn*8 + 2*t;
            *(float2*)&g_A[((size_t)b*SEQ + r0    )*DMODEL + col] =
                make_float2(tf32r(o[mi][vn][0]*iA), tf32r(o[mi][vn][1]*iA));
            *(float2*)&g_A[((size_t)b*SEQ + r0 + 8)*DMODEL + col] =
                make_float2(tf32r(o[mi][vn][2]*iB), tf32r(o[mi][vn][3]*iB));
        }
    }
}

// ---------------- launch ----------------------------------------------------------
extern "C" void kernel_launch(void* const* d_in, const int* in_sizes, int n_in,
                              void* d_out, int out_size)
{
    const float* X  = (const float*)d_in[0];
    const float* Wq = (const float*)d_in[1];
    const float* bq = (const float*)d_in[2];
    const float* Wk = (const float*)d_in[3];
    const float* bk = (const float*)d_in[4];
    const float* Wv = (const float*)d_in[5];
    const float* bv = (const float*)d_in[6];
    const float* Wo = (const float*)d_in[7];
    const float* bo = (const float*)d_in[8];
    float* out = (float*)d_out;

    static int attr_done = 0;
    if (!attr_done) {
        cudaFuncSetAttribute(gemm_mma, cudaFuncAttributeMaxDynamicSharedMemorySize, SM_BYTES);
        cudaFuncSetAttribute(attn_mma, cudaFuncAttributeMaxDynamicSharedMemorySize, ATT_SMEM);
        attr_done = 1;
    }

    round_all<<<(NTOT4 + 255)/256, 256>>>(X, Wq, Wk, Wv, Wo);

    dim3 gQKV(3*DMODEL/128, MROWS/128);          // 18 x 64
    gemm_mma<<<gQKV, 128, SM_BYTES>>>(bq, bk, bv, nullptr, 0);

    dim3 gAttn(SEQ/128, BATCH*NHEAD);            // 8 x 128
    attn_mma<<<gAttn, 128, ATT_SMEM>>>();

    dim3 gO(DMODEL/128, MROWS/128);              // 6 x 64
    gemm_mma<<<gO, 128, SM_BYTES>>>(bo, nullptr, nullptr, out, 1);
}

// round 17
// speedup vs baseline: 8.2643x; 1.1674x over previous
#include <cuda_runtime.h>
#include <cuda_pipeline.h>
#include <cstdint>
#include <math.h>

#define BATCH 8
#define SEQ 1024
#define DMODEL 768
#define NHEAD 16
#define HDIM 48
#define MROWS (BATCH*SEQ)

// ---------------- scratch (allocation-free rule: device globals) -----------------
__device__ float g_Q[MROWS*DMODEL];        // [B,H,S,PD] tf32-rounded
__device__ float g_K[MROWS*DMODEL];        // [B,H,S,PD] tf32-rounded
__device__ float g_V[MROWS*DMODEL];        // [B,H,S,PD] tf32-rounded
__device__ float g_A[MROWS*DMODEL];        // [B,S,D]   tf32-rounded
__device__ float g_Xr[MROWS*DMODEL];       // X tf32-rounded
__device__ float g_Wr[3*DMODEL*DMODEL];    // Wq,Wk,Wv tf32-rounded
__device__ float g_WoR[DMODEL*DMODEL];     // Wo tf32-rounded

// ---------------- helpers ---------------------------------------------------------
__device__ __forceinline__ float tf32r(float x) {
    uint32_t r; asm("cvt.rna.tf32.f32 %0, %1;" : "=r"(r) : "f"(x));
    return __uint_as_float(r);
}
__device__ __forceinline__ void mma8(float& c0, float& c1, float& c2, float& c3,
                                     uint32_t a0, uint32_t a1, uint32_t a2, uint32_t a3,
                                     uint32_t b0, uint32_t b1) {
    asm volatile("mma.sync.aligned.m16n8k8.row.col.f32.tf32.tf32.f32 "
                 "{%0,%1,%2,%3}, {%4,%5,%6,%7}, {%8,%9}, {%0,%1,%2,%3};"
                 : "+f"(c0), "+f"(c1), "+f"(c2), "+f"(c3)
                 : "r"(a0), "r"(a1), "r"(a2), "r"(a3), "r"(b0), "r"(b1));
}

// ---------------- fused tf32 pre-rounding (X, Wq, Wk, Wv, Wo in one launch) -------
#define NX4 (MROWS*DMODEL/4)
#define NW4 (DMODEL*DMODEL/4)
#define NTOT4 (NX4 + 4*NW4)

__global__ __launch_bounds__(256)
void round_all(const float* __restrict__ X,  const float* __restrict__ Wq,
               const float* __restrict__ Wk, const float* __restrict__ Wv,
               const float* __restrict__ Wo)
{
    const int i = blockIdx.x*256 + threadIdx.x;
    if (i >= NTOT4) return;
    const float4* src; float4* dst; int off;
    if (i < NX4) { src = (const float4*)X; dst = (float4*)g_Xr; off = i; }
    else {
        const int j = i - NX4, which = j / NW4; off = j - which*NW4;
        src = (const float4*)((which == 0) ? Wq : (which == 1) ? Wk :
                              (which == 2) ? Wv : Wo);
        dst = (which < 3) ? (float4*)(g_Wr + (size_t)which*DMODEL*DMODEL)
                          : (float4*)g_WoR;
    }
    float4 v = src[off];
    v.x = tf32r(v.x); v.y = tf32r(v.y); v.z = tf32r(v.z); v.w = tf32r(v.w);
    dst[off] = v;
}

// ---------------- manual mma GEMM: 128x128 CTA, 4 warps 64x64, BK=16, 4 stages ----
#define BK 16
#define NKIT (DMODEL/BK)   // 48
#define LDA 20     // A-frag bank = (20g+t)%32 bijective -> conflict-free
#define LDB 136    // B-frag bank = 8t+g               -> conflict-free
#define LDC 132
#define ASZ (128*LDA)      // 2560 floats / stage
#define BSZ (BK*LDB)       // 2176 floats / stage
#define STG (ASZ + BSZ)
#define SM_BYTES (4*STG*4) // 75776 B ; epilogue stage 128*132*4 = 67584 fits

__global__ __launch_bounds__(128, 2)
void gemm_mma(const float* __restrict__ b0p, const float* __restrict__ b1p,
              const float* __restrict__ b2p, float* __restrict__ outp, int mode)
{
    extern __shared__ float smem[];

    const int tid  = threadIdx.x;
    const int warp = tid >> 5, lane = tid & 31;
    const int g    = lane >> 2, t = lane & 3;
    const int wm   = warp >> 1, wn = warp & 1;

    const int mTile = blockIdx.y * 128;
    const int nGlob = blockIdx.x * 128;

    const float* A; const float* B; const float* bias; int nTile;
    if (mode == 0) {
        const int which = nGlob / DMODEL;
        A    = g_Xr;
        B    = g_Wr + (size_t)which*DMODEL*DMODEL;
        bias = (which == 0) ? b0p : (which == 1) ? b1p : b2p;
        nTile = nGlob - which*DMODEL;
    } else { A = g_A; B = g_WoR; bias = b0p; nTile = nGlob; }

    float c[4][8][4];
    #pragma unroll
    for (int mi = 0; mi < 4; mi++)
        #pragma unroll
        for (int ni = 0; ni < 8; ni++)
            { c[mi][ni][0]=0.f; c[mi][ni][1]=0.f; c[mi][ni][2]=0.f; c[mi][ni][3]=0.f; }

    const int aRow = tid >> 2, aC4 = (tid & 3) << 2;   // A: 128x16 = 512 f4, 4/thread
    const int bRow = tid >> 5, bC4 = (tid & 31) << 2;  // B: 16x128 = 512 f4, 4/thread

    auto load_stage = [&](int s) {
        float* As = smem + (s & 3)*STG;
        float* Bs = As + ASZ;
        const int k0 = s*BK;
        #pragma unroll
        for (int i = 0; i < 4; i++) {
            const int row = aRow + i*32;
            __pipeline_memcpy_async(&As[row*LDA + aC4],
                                    &A[(size_t)(mTile + row)*DMODEL + k0 + aC4], 16);
        }
        #pragma unroll
        for (int i = 0; i < 4; i++) {
            const int row = bRow + i*4;
            __pipeline_memcpy_async(&Bs[row*LDB + bC4],
                                    &B[(size_t)(k0 + row)*DMODEL + nTile + bC4], 16);
        }
    };

    load_stage(0); __pipeline_commit();
    load_stage(1); __pipeline_commit();
    load_stage(2); __pipeline_commit();

    for (int kc = 0; kc < NKIT; kc++) {
        if (kc <= NKIT-3)      __pipeline_wait_prior(2);
        else if (kc == NKIT-2) __pipeline_wait_prior(1);
        else                   __pipeline_wait_prior(0);
        __syncthreads();                      // stage kc visible; all warps past compute(kc-1)

        if (kc + 3 < NKIT) { load_stage(kc + 3); __pipeline_commit(); }

        const float* As = smem + (kc & 3)*STG;
        const float* Bs = As + ASZ;
        #pragma unroll
        for (int kk = 0; kk < BK/8; kk++) {
            uint32_t a[4][4], b[8][2];
            #pragma unroll
            for (int mi = 0; mi < 4; mi++) {
                const float* ar = &As[(wm*64 + mi*16)*LDA + kk*8];
                a[mi][0] = __float_as_uint(ar[(g    )*LDA + t    ]);
                a[mi][1] = __float_as_uint(ar[(g + 8)*LDA + t    ]);
                a[mi][2] = __float_as_uint(ar[(g    )*LDA + t + 4]);
                a[mi][3] = __float_as_uint(ar[(g + 8)*LDA + t + 4]);
            }
            #pragma unroll
            for (int ni = 0; ni < 8; ni++) {
                const float* br = &Bs[kk*8*LDB + wn*64 + ni*8 + g];
                b[ni][0] = __float_as_uint(br[ t     *LDB]);
                b[ni][1] = __float_as_uint(br[(t + 4)*LDB]);
            }
            #pragma unroll
            for (int mi = 0; mi < 4; mi++)
                #pragma unroll
                for (int ni = 0; ni < 8; ni++)
                    mma8(c[mi][ni][0], c[mi][ni][1], c[mi][ni][2], c[mi][ni][3],
                         a[mi][0], a[mi][1], a[mi][2], a[mi][3],
                         b[ni][0], b[ni][1]);
        }
    }
    __syncthreads();

    // stage accum -> smem, then coalesced remap stores
    float* stage = smem;
    #pragma unroll
    for (int mi = 0; mi < 4; mi++)
        #pragma unroll
        for (int ni = 0; ni < 8; ni++) {
            const int col = wn*64 + ni*8 + 2*t;
            *(float2*)&stage[(wm*64 + mi*16 + g    )*LDC + col] =
                make_float2(c[mi][ni][0], c[mi][ni][1]);
            *(float2*)&stage[(wm*64 + mi*16 + g + 8)*LDC + col] =
                make_float2(c[mi][ni][2], c[mi][ni][3]);
        }
    __syncthreads();

    if (mode == 0) {
        const int which = nGlob / DMODEL;
        float* outg = (which == 0) ? g_Q : (which == 1) ? g_K : g_V;
        #pragma unroll
        for (int it = 0; it < 32; it++) {
            const int gg = tid + it*128;
            const int row = gg >> 5, cc = (gg & 31) << 2;
            float4 v = *(float4*)&stage[row*LDC + cc];
            const int np = nTile + cc;
            const int h = np / HDIM, pd = np % HDIM;
            const float4 bb = *(const float4*)&bias[np];
            v.x = tf32r(v.x + bb.x); v.y = tf32r(v.y + bb.y);
            v.z = tf32r(v.z + bb.z); v.w = tf32r(v.w + bb.w);
            const int m = mTile + row;
            const int b = m >> 10, s = m & 1023;
            *(float4*)&outg[(((size_t)b*NHEAD + h)*SEQ + s)*HDIM + pd] = v;
        }
    } else {
        #pragma unroll
        for (int it = 0; it < 32; it++) {
            const int gg = tid + it*128;
            const int row = gg >> 5, cc = (gg & 31) << 2;
            float4 v = *(float4*)&stage[row*LDC + cc];
            const float4 bb = *(const float4*)&bias[nTile + cc];
            v.x += bb.x; v.y += bb.y; v.z += bb.z; v.w += bb.w;
            *(float4*)&outp[(size_t)(mTile + row)*DMODEL + nTile + cc] = v;
        }
    }
}

// ---------------- Flash attention: shuffle P->A-frag, double-buffered K/V ---------
#define KT 32
#define NKT (SEQ/KT)   // 32
#define QS 52    // K/Q frag bank = 4g+t   conflict-free
#define VS 56    // V frag bank  = 24t+g   conflict-free
#define KSZ (KT*QS)
#define VSZ (KT*VS)
#define ATT_SMEM ((128*QS + 2*KSZ + 2*VSZ) * 4)   // 54272 B

__global__ __launch_bounds__(128, 2)
void attn_mma()
{
    extern __shared__ float sm[];
    float* sQ  = sm;                    // [128][QS]
    float* sKb = sQ + 128*QS;           // 2 x [KT][QS]
    float* sVb = sKb + 2*KSZ;           // 2 x [KT][VS]

    const int bh = blockIdx.y;
    const int q0 = blockIdx.x * 128;
    const float* Qp = g_Q + (size_t)bh * SEQ * HDIM;
    const float* Kp = g_K + (size_t)bh * SEQ * HDIM;
    const float* Vp = g_V + (size_t)bh * SEQ * HDIM;

    const int tid  = threadIdx.x;
    const int w    = tid >> 5, lane = tid & 31;
    const int g    = lane >> 2, t = lane & 3;
    const int wr   = w * 32;

    auto load_kv = [&](int s) {
        float* sK = sKb + (s & 1)*KSZ;
        float* sV = sVb + (s & 1)*VSZ;
        for (int i = tid; i < KT*12; i += 128) {
            const int row = i / 12, c4 = (i % 12) << 2;
            __pipeline_memcpy_async(&sK[row*QS + c4],
                                    &Kp[(size_t)(s*KT + row)*HDIM + c4], 16);
            __pipeline_memcpy_async(&sV[row*VS + c4],
                                    &Vp[(size_t)(s*KT + row)*HDIM + c4], 16);
        }
    };

    load_kv(0); __pipeline_commit();

    for (int i = tid; i < 128*12; i += 128) {
        const int row = i / 12, c4 = (i % 12) << 2;
        *(float4*)&sQ[row*QS + c4] = *(const float4*)&Qp[(size_t)(q0 + row)*HDIM + c4];
    }
    __syncthreads();

    // persistent Q A-fragments: 2 m16-frags (rows wr..wr+31), 6 k-chunks
    uint32_t qa[2][6][4];
    #pragma unroll
    for (int mi = 0; mi < 2; mi++)
        #pragma unroll
        for (int kc = 0; kc < 6; kc++) {
            const float* qr = &sQ[(wr + mi*16)*QS + kc*8];
            qa[mi][kc][0] = __float_as_uint(qr[(g    )*QS + t    ]);
            qa[mi][kc][1] = __float_as_uint(qr[(g + 8)*QS + t    ]);
            qa[mi][kc][2] = __float_as_uint(qr[(g    )*QS + t + 4]);
            qa[mi][kc][3] = __float_as_uint(qr[(g + 8)*QS + t + 4]);
        }

    float mrow[4], lrow[4];
    #pragma unroll
    for (int i = 0; i < 4; i++) { mrow[i] = -1e30f; lrow[i] = 0.f; }
    float o[2][6][4];
    #pragma unroll
    for (int mi = 0; mi < 2; mi++)
        #pragma unroll
        for (int vn = 0; vn < 6; vn++)
            { o[mi][vn][0]=0.f; o[mi][vn][1]=0.f; o[mi][vn][2]=0.f; o[mi][vn][3]=0.f; }

    const float scale = rsqrtf((float)HDIM);

    for (int kt = 0; kt < NKT; kt++) {
        __pipeline_wait_prior(0);         // stage kt arrived (issued one iter ago)
        __syncthreads();                  // visible to all; all warps past compute(kt-1)

        if (kt + 1 < NKT) { load_kv(kt + 1); __pipeline_commit(); }

        const float* sK = sKb + (kt & 1)*KSZ;
        const float* sV = sVb + (kt & 1)*VSZ;

        // S = Q K^T : 32x32 per warp -> s[2][4][4]
        float s[2][4][4];
        #pragma unroll
        for (int mi = 0; mi < 2; mi++)
            #pragma unroll
            for (int nf = 0; nf < 4; nf++)
                { s[mi][nf][0]=0.f; s[mi][nf][1]=0.f; s[mi][nf][2]=0.f; s[mi][nf][3]=0.f; }
        #pragma unroll
        for (int kc = 0; kc < 6; kc++)
            #pragma unroll
            for (int nf = 0; nf < 4; nf++) {
                const uint32_t b0 = __float_as_uint(sK[(nf*8 + g)*QS + kc*8 + t    ]);
                const uint32_t b1 = __float_as_uint(sK[(nf*8 + g)*QS + kc*8 + t + 4]);
                #pragma unroll
                for (int mi = 0; mi < 2; mi++)
                    mma8(s[mi][nf][0], s[mi][nf][1], s[mi][nf][2], s[mi][nf][3],
                         qa[mi][kc][0], qa[mi][kc][1], qa[mi][kc][2], qa[mi][kc][3],
                         b0, b1);
            }

        // online softmax over 4 row-groups: rows wr+g + {0,8,16,24}
        #pragma unroll
        for (int ri = 0; ri < 4; ri++) {
            const int mi = ri >> 1, hh = (ri & 1) * 2;
            float mx = -1e30f;
            #pragma unroll
            for (int nf = 0; nf < 4; nf++) {
                s[mi][nf][hh]   *= scale;
                s[mi][nf][hh+1] *= scale;
                mx = fmaxf(mx, fmaxf(s[mi][nf][hh], s[mi][nf][hh+1]));
            }
            mx = fmaxf(mx, __shfl_xor_sync(0xffffffffu, mx, 1));
            mx = fmaxf(mx, __shfl_xor_sync(0xffffffffu, mx, 2));
            const float mn = fmaxf(mrow[ri], mx);
            const float cr = __expf(mrow[ri] - mn);
            mrow[ri] = mn;
            float sum = 0.f;
            #pragma unroll
            for (int nf = 0; nf < 4; nf++) {
                const float p0 = __expf(s[mi][nf][hh]   - mn);
                const float p1 = __expf(s[mi][nf][hh+1] - mn);
                sum += p0 + p1;
                s[mi][nf][hh]   = tf32r(p0);
                s[mi][nf][hh+1] = tf32r(p1);
            }
            sum += __shfl_xor_sync(0xffffffffu, sum, 1);
            sum += __shfl_xor_sync(0xffffffffu, sum, 2);
            lrow[ri] = lrow[ri]*cr + sum;
            #pragma unroll
            for (int vn = 0; vn < 6; vn++) {
                o[mi][vn][hh]   *= cr;
                o[mi][vn][hh+1] *= cr;
            }
        }

        // O += P V : convert S-frag -> A-frag via shfl (no smem round trip)
        const int L1 = 4*g + (t >> 1);
        const int L2 = L1 + 2;
        const bool odd = (t & 1);
        #pragma unroll
        for (int nf = 0; nf < 4; nf++) {
            #pragma unroll
            for (int mi = 0; mi < 2; mi++) {
                const float e0 = __shfl_sync(0xffffffffu, s[mi][nf][0], L1);
                const float o0 = __shfl_sync(0xffffffffu, s[mi][nf][1], L1);
                const float e1 = __shfl_sync(0xffffffffu, s[mi][nf][2], L1);
                const float o1 = __shfl_sync(0xffffffffu, s[mi][nf][3], L1);
                const float e2 = __shfl_sync(0xffffffffu, s[mi][nf][0], L2);
                const float o2 = __shfl_sync(0xffffffffu, s[mi][nf][1], L2);
                const float e3 = __shfl_sync(0xffffffffu, s[mi][nf][2], L2);
                const float o3 = __shfl_sync(0xffffffffu, s[mi][nf][3], L2);
                const uint32_t a0 = __float_as_uint(odd ? o0 : e0);
                const uint32_t a1 = __float_as_uint(odd ? o1 : e1);
                const uint32_t a2 = __float_as_uint(odd ? o2 : e2);
                const uint32_t a3 = __float_as_uint(odd ? o3 : e3);
                #pragma unroll
                for (int vn = 0; vn < 6; vn++) {
                    const uint32_t b0 = __float_as_uint(sV[(nf*8 + t    )*VS + vn*8 + g]);
                    const uint32_t b1 = __float_as_uint(sV[(nf*8 + t + 4)*VS + vn*8 + g]);
                    mma8(o[mi][vn][0], o[mi][vn][1], o[mi][vn][2], o[mi][vn][3],
                         a0, a1, a2, a3, b0, b1);
                }
            }
        }
    }

    // epilogue -> g_A [B,S,D], tf32-rounded for the O-projection
    const int b = bh >> 4, h = bh & 15;
    const float inv0 = 1.f / lrow[0], inv1 = 1.f / lrow[1];
    const float inv2 = 1.f / lrow[2], inv3 = 1.f / lrow[3];
    #pragma unroll
    for (int mi = 0; mi < 2; mi++) {
        const int r0 = q0 + wr + mi*16 + g;
        const float iA = mi ? inv2 : inv0;
        const float iB = mi ? inv3 : inv1;
        #pragma unroll
        for (int vn = 0; vn < 6; vn++) {
            const int col = h*HDIM + vn*8 + 2*t;
            *(float2*)&g_A[((size_t)b*SEQ + r0    )*DMODEL + col] =
                make_float2(tf32r(o[mi][vn][0]*iA), tf32r(o[mi][vn][1]*iA));
            *(float2*)&g_A[((size_t)b*SEQ + r0 + 8)*DMODEL + col] =
                make_float2(tf32r(o[mi][vn][2]*iB), tf32r(o[mi][vn][3]*iB));
        }
    }
}

// ---------------- launch ----------------------------------------------------------
extern "C" void kernel_launch(void* const* d_in, const int* in_sizes, int n_in,
                              void* d_out, int out_size)
{
    const float* X  = (const float*)d_in[0];
    const float* Wq = (const float*)d_in[1];
    const float* bq = (const float*)d_in[2];
    const float* Wk = (const float*)d_in[3];
    const float* bk = (const float*)d_in[4];
    const float* Wv = (const float*)d_in[5];
    const float* bv = (const float*)d_in[6];
    const float* Wo = (const float*)d_in[7];
    const float* bo = (const float*)d_in[8];
    float* out = (float*)d_out;

    static int attr_done = 0;
    if (!attr_done) {
        cudaFuncSetAttribute(gemm_mma, cudaFuncAttributeMaxDynamicSharedMemorySize, SM_BYTES);
        cudaFuncSetAttribute(attn_mma, cudaFuncAttributeMaxDynamicSharedMemorySize, ATT_SMEM);
        attr_done = 1;
    }

    round_all<<<(NTOT4 + 255)/256, 256>>>(X, Wq, Wk, Wv, Wo);

    dim3 gQKV(3*DMODEL/128, MROWS/128);          // 18 x 64
    gemm_mma<<<gQKV, 128, SM_BYTES>>>(bq, bk, bv, nullptr, 0);

    dim3 gAttn(SEQ/128, BATCH*NHEAD);            // 8 x 128
    attn_mma<<<gAttn, 128, ATT_SMEM>>>();

    dim3 gO(DMODEL/128, MROWS/128);              // 6 x 64
    gemm_mma<<<gO, 128, SM_BYTES>>>(bo, nullptr, nullptr, out, 1);
}